// round 7
// baseline (speedup 1.0000x reference)
#include <cuda_runtime.h>

// IF spiking neuron forward: T=8 scan, soft reset, spike = thresh * (mem >= thresh).
// x: [T*B, C, H, W] f32 (T=8, timestep stride = total/8 elements), thresh: [1] f32.
// Per neuron: mem = 0.5*thr; for t: m = mem + x[t]; sp = (m>=thr)?thr:0; out[t]=sp; mem=m-sp.
//
// Pure HBM-streaming (268 MB traffic, zero reuse). Findings:
//   R0: one-shot 4096x256, front-batched loads -> 37.5us ncu
//   R1: persistent grid-stride -> 53.6us (MLP collapse; REJECTED)
//   R2: .cs evict-first hints  -> 45.6us (L1tex overhead; REJECTED)
//   R3: 512-thread CTAs        -> 36.8us (WIN)
//   R5: store-in-scan          -> 36.1us, 7.43 TB/s e2e (WIN, current base)
// R6: CTA size 512 -> 1024 (same 64 warps/SM, half the CTA-boundary events).

#ifndef IF_T
#define IF_T 8
#endif

__global__ __launch_bounds__(1024, 2)
void if_scan_kernel(const float4* __restrict__ x,
                    const float* __restrict__ thresh,
                    float4* __restrict__ out,
                    int stride_vec)
{
    const int n = blockIdx.x * blockDim.x + threadIdx.x;  // exact cover: grid*block == n_vec

    const float thr = __ldg(thresh);

    // Front-batch all T independent loads (MLP=8, 128B in flight per thread)
    float4 v[IF_T];
#pragma unroll
    for (int t = 0; t < IF_T; ++t)
        v[t] = x[(size_t)t * stride_vec + n];

    float mx = 0.5f * thr, my = 0.5f * thr, mz = 0.5f * thr, mw = 0.5f * thr;

    // Scan with per-step store: out[t] leaves as soon as v[t] has arrived and
    // the 12-op ALU chain for step t is done; later loads still outstanding.
#pragma unroll
    for (int t = 0; t < IF_T; ++t) {
        mx += v[t].x; my += v[t].y; mz += v[t].z; mw += v[t].w;
        float sx = (mx >= thr) ? thr : 0.0f;
        float sy = (my >= thr) ? thr : 0.0f;
        float sz = (mz >= thr) ? thr : 0.0f;
        float sw = (mw >= thr) ? thr : 0.0f;
        float4 sp; sp.x = sx; sp.y = sy; sp.z = sz; sp.w = sw;
        out[(size_t)t * stride_vec + n] = sp;
        mx -= sx; my -= sy; mz -= sz; mw -= sw;
    }
}

extern "C" void kernel_launch(void* const* d_in, const int* in_sizes, int n_in,
                              void* d_out, int out_size)
{
    const float* x      = (const float*)d_in[0];
    const float* thresh = (const float*)d_in[1];
    float* out          = (float*)d_out;

    const int total = in_sizes[0];          // T*B*C*H*W = 33,554,432
    const int stride = total / IF_T;        // per-timestep elements = 4,194,304
    const int stride_vec = stride / 4;      // float4 units = 1,048,576 = 2^20

    const int threads = 1024;
    const int blocks = stride_vec / threads;  // 1024, exact cover

    if_scan_kernel<<<blocks, threads>>>((const float4*)x, thresh,
                                        (float4*)out, stride_vec);
}

// round 8
// speedup vs baseline: 1.0464x; 1.0464x over previous
#include <cuda_runtime.h>

// IF spiking neuron forward: T=8 scan, soft reset, spike = thresh * (mem >= thresh).
// x: [T*B, C, H, W] f32 (T=8, timestep stride = total/8 elements), thresh: [1] f32.
// Per neuron: mem = 0.5*thr; for t: m = mem + x[t]; sp = (m>=thr)?thr:0; out[t]=sp; mem=m-sp.
//
// Pure HBM-streaming (268 MB traffic, zero reuse). Search history:
//   R0: one-shot 4096x256, front-batched loads -> 37.5us ncu
//   R1: persistent grid-stride -> 53.6us (SM-wide MLP collapse; REJECTED)
//   R2: .cs evict-first hints  -> 45.6us (L1tex path overhead;  REJECTED)
//   R3: 512-thread CTAs        -> 36.8us (WIN)
//   R5: store-in-scan          -> 36.1us, 7.43 TB/s e2e = 93% of spec (WIN)
//   R6: 1024-thread CTAs       -> 36.8us (occ granularity loss; REJECTED)
// R7 == R5 (final): 512x2048, MLP=8 front-batched loads, per-step stores
// overlapping the write drain with the read-latency shadow.

#ifndef IF_T
#define IF_T 8
#endif

__global__ __launch_bounds__(512, 4)
void if_scan_kernel(const float4* __restrict__ x,
                    const float* __restrict__ thresh,
                    float4* __restrict__ out,
                    int stride_vec)
{
    const int n = blockIdx.x * blockDim.x + threadIdx.x;  // exact cover: grid*block == n_vec

    const float thr = __ldg(thresh);

    // Front-batch all T independent loads (MLP=8, 128B in flight per thread)
    float4 v[IF_T];
#pragma unroll
    for (int t = 0; t < IF_T; ++t)
        v[t] = x[(size_t)t * stride_vec + n];

    float mx = 0.5f * thr, my = 0.5f * thr, mz = 0.5f * thr, mw = 0.5f * thr;

    // Scan with per-step store: out[t] leaves as soon as v[t] has arrived and
    // the 12-op ALU chain for step t is done; later loads still outstanding.
#pragma unroll
    for (int t = 0; t < IF_T; ++t) {
        mx += v[t].x; my += v[t].y; mz += v[t].z; mw += v[t].w;
        float sx = (mx >= thr) ? thr : 0.0f;
        float sy = (my >= thr) ? thr : 0.0f;
        float sz = (mz >= thr) ? thr : 0.0f;
        float sw = (mw >= thr) ? thr : 0.0f;
        float4 sp; sp.x = sx; sp.y = sy; sp.z = sz; sp.w = sw;
        out[(size_t)t * stride_vec + n] = sp;
        mx -= sx; my -= sy; mz -= sz; mw -= sw;
    }
}

extern "C" void kernel_launch(void* const* d_in, const int* in_sizes, int n_in,
                              void* d_out, int out_size)
{
    const float* x      = (const float*)d_in[0];
    const float* thresh = (const float*)d_in[1];
    float* out          = (float*)d_out;

    const int total = in_sizes[0];          // T*B*C*H*W = 33,554,432
    const int stride = total / IF_T;        // per-timestep elements = 4,194,304
    const int stride_vec = stride / 4;      // float4 units = 1,048,576 = 2^20

    const int threads = 512;
    const int blocks = stride_vec / threads;  // 2048, exact cover

    if_scan_kernel<<<blocks, threads>>>((const float4*)x, thresh,
                                        (float4*)out, stride_vec);
}